// round 14
// baseline (speedup 1.0000x reference)
#include <cuda_runtime.h>
#include <cuda_fp16.h>
#include <cstdint>

#define B_  4
#define T_  512
#define G_  129
#define F_  96
#define O_  96

#define HM  128
#define HROWS 130
#define XROWB 208                       // bytes per fp16 x row: 192 data + 16 pad (52 units == 20 mod 32)
#define XB_BYTES (HROWS * XROWB)        // 27040 per WG
#define STG_BYTES (HROWS * 96 * 4)      // 49920 fp32 staging per WG

#define WBLKB 3072                      // per (kk,step) W block: 2 planes x 32 slots x 48B
#define WS_BYTES (18 * WBLKB)           // 55296

#define SM_X0  WS_BYTES
#define SM_ST0 (SM_X0 + 2 * XB_BYTES)
#define SMEM_TOTAL (WS_BYTES + 2 * XB_BYTES + 2 * STG_BYTES)   // 209216

#define NTHREADS 512

__device__ __forceinline__ uint32_t smem_u32(const void* p) {
    uint32_t a;
    asm("{ .reg .u64 t; cvta.to.shared.u64 t, %1; cvt.u32.u64 %0, t; }" : "=r"(a) : "l"(p));
    return a;
}
__device__ __forceinline__ void cp_async16z(uint32_t saddr, const void* gptr, uint32_t src_sz) {
    asm volatile("cp.async.cg.shared.global [%0], [%1], 16, %2;"
                 :: "r"(saddr), "l"(gptr), "r"(src_sz));
}
// pack two fp32 -> fp16x2 (lo in low half), round-to-nearest
__device__ __forceinline__ uint32_t pack_f16x2(float lo, float hi) {
    uint32_t r;
    asm("cvt.rn.f16x2.f32 %0, %2, %1;" : "=r"(r) : "f"(lo), "f"(hi));
    return r;
}

__device__ __forceinline__ void mma_f16(float c[4], uint32_t a0, uint32_t a1, uint32_t a2,
                                        uint32_t a3, uint32_t b0, uint32_t b1) {
    asm volatile(
        "mma.sync.aligned.m16n8k16.row.col.f32.f16.f16.f32 "
        "{%0,%1,%2,%3}, {%4,%5,%6,%7}, {%8,%9}, {%0,%1,%2,%3};"
        : "+f"(c[0]), "+f"(c[1]), "+f"(c[2]), "+f"(c[3])
        : "r"(a0), "r"(a1), "r"(a2), "r"(a3), "r"(b0), "r"(b1));
}

__global__ __launch_bounds__(NTHREADS, 1)
void conv1d_mma_kernel(const float* __restrict__ x,
                       const float* __restrict__ w,
                       const float* __restrict__ bias,
                       float* __restrict__ out)
{
    extern __shared__ char smc[];
    char* ws_b = smc;                                   // W fp16, slot layout
    const int tid = threadIdx.x, wid = tid >> 5, lane = tid & 31;
    const int wg = wid >> 3;
    const int tid2 = tid & 255;
    const int wl = wid & 7;
    const int wm = wl & 3, wn = wl >> 2;                // 4 M-warps x 2 N-warps
    const int lane4 = lane >> 2, lc = lane & 3;
    const int g = blockIdx.x;

    char* xb_b = smc + SM_X0 + wg * XB_BYTES;           // this WG's fp16 x buffer
    float* stg = (float*)(smc + SM_ST0 + wg * STG_BYTES);
    const uint32_t stg_s = smem_u32(stg);

    // ---- W[g] -> smem fp16 (rna), slot layout, once per CTA
    {
        const float4* wg4 = (const float4*)(w + (size_t)g * (O_ * F_ * 3));
        for (int q = tid; q < (O_ * F_ * 3) / 4; q += NTHREADS) {
            float4 v = wg4[q];
            int e = q * 4;
            int o = e / (F_ * 3);
            int rem = e - o * (F_ * 3);                  // o fixed across the 4
            int nblk = o >> 3, orow = o & 7;
            int pos = (nblk < 4) ? nblk : (nblk < 6 ? nblk + 4 : (nblk < 10 ? nblk - 2 : nblk));
            const float* vf = (const float*)&v;
            #pragma unroll
            for (int j = 0; j < 4; ++j) {
                int rr = rem + j;
                int f = rr / 3, kk = rr - 3 * f;
                int s = f >> 4, fh = f & 15;
                int plane = fh >> 3, kp = (fh & 7) >> 1, klo = fh & 1;
                int slot = orow * 4 + kp;
                int off = (kk * 6 + s) * WBLKB + plane * 1536 + slot * 48 + pos * 4 + klo * 2;
                *(__half*)(ws_b + off) = __float2half_rn(vf[j]);
            }
        }
    }

    // ---- bias in registers
    float bias0[6], bias1[6];
    {
        const float* bg = bias + g * O_ + wn * 48 + 2 * lc;
        #pragma unroll
        for (int jn = 0; jn < 6; ++jn) { bias0[jn] = bg[jn * 8]; bias1[jn] = bg[jn * 8 + 1]; }
    }

    __syncthreads();                                    // W visible to both WGs

    const char* paw = xb_b + (wm * 32 + lane4) * XROWB + lc * 4;
    const char* pbl = ws_b + lane * 48;
    const int barid = wg + 1;

    // ---- prefetch first window's fp32 into staging
    {
        const int h = wg, bb = h >> 2, t0 = (h & 3) * HM;
        const float* xgb = x + (((size_t)bb * T_) * G_ + g) * F_;
        for (int q = tid2; q < HROWS * 24; q += 256) {
            int p = q / 24, c = q - p * 24;
            int t = t0 - 1 + p;
            uint32_t ok = (t >= 0 && t < T_) ? 16u : 0u;
            cp_async16z(stg_s + p * 384 + c * 16, xgb + (size_t)t * (G_ * F_) + c * 4, ok);
        }
        asm volatile("cp.async.commit_group;" ::: "memory");
    }

    // ---- 8 half-windows per WG: h = 2*i + wg
    for (int i = 0; i < 8; ++i) {
        const int h = 2 * i + wg;

        asm volatile("cp.async.wait_group 0;" ::: "memory");
        asm volatile("bar.sync %0, 256;" :: "r"(barid) : "memory");   // stage ready, x buf free

        // convert staging fp32 -> fp16 x buffer (smem -> smem, no global latency)
        for (int q = tid2; q < HROWS * 24; q += 256) {
            int p = q / 24, c = q - p * 24;
            float4 v = *(const float4*)(stg + p * 96 + c * 4);
            *(uint2*)(xb_b + p * XROWB + c * 8) =
                make_uint2(pack_f16x2(v.x, v.y), pack_f16x2(v.z, v.w));
        }
        asm volatile("bar.sync %0, 256;" :: "r"(barid) : "memory");   // x buf ready, stage free

        // prefetch next window into staging (overlaps entire compute below)
        if (i < 7) {
            const int hn = h + 2, bb = hn >> 2, t0 = (hn & 3) * HM;
            const float* xgb = x + (((size_t)bb * T_) * G_ + g) * F_;
            for (int q = tid2; q < HROWS * 24; q += 256) {
                int p = q / 24, c = q - p * 24;
                int t = t0 - 1 + p;
                uint32_t ok = (t >= 0 && t < T_) ? 16u : 0u;
                cp_async16z(stg_s + p * 384 + c * 16, xgb + (size_t)t * (G_ * F_) + c * 4, ok);
            }
            asm volatile("cp.async.commit_group;" ::: "memory");
        }

        // accumulators from bias
        float acc[2][6][4];
        #pragma unroll
        for (int jn = 0; jn < 6; ++jn) {
            #pragma unroll
            for (int mb = 0; mb < 2; ++mb) {
                acc[mb][jn][0] = bias0[jn]; acc[mb][jn][1] = bias1[jn];
                acc[mb][jn][2] = bias0[jn]; acc[mb][jn][3] = bias1[jn];
            }
        }

        // mainloop: warp tile m32 x n48, 3 shifts x 6 K16-steps, fully unrolled
        #pragma unroll
        for (int kk = 0; kk < 3; ++kk) {
            #pragma unroll
            for (int s = 0; s < 6; ++s) {
                const char* pbs = pbl + (kk * 6 + s) * WBLKB;
                uint4 q0 = *(const uint4*)(pbs + wn * 16);
                uint2 q1 = *(const uint2*)(pbs + 32 + wn * 8);
                uint4 q2 = *(const uint4*)(pbs + 1536 + wn * 16);
                uint2 q3 = *(const uint2*)(pbs + 1536 + 32 + wn * 8);
                uint32_t b0f[6] = { q0.x, q0.y, q0.z, q0.w, q1.x, q1.y };
                uint32_t b1f[6] = { q2.x, q2.y, q2.z, q2.w, q3.x, q3.y };

                const char* pam = paw + kk * XROWB + s * 32;
                uint32_t a00 = *(const uint32_t*)(pam);
                uint32_t a02 = *(const uint32_t*)(pam + 16);
                uint32_t a01 = *(const uint32_t*)(pam + 8 * XROWB);
                uint32_t a03 = *(const uint32_t*)(pam + 8 * XROWB + 16);
                uint32_t a10 = *(const uint32_t*)(pam + 16 * XROWB);
                uint32_t a12 = *(const uint32_t*)(pam + 16 * XROWB + 16);
                uint32_t a11 = *(const uint32_t*)(pam + 24 * XROWB);
                uint32_t a13 = *(const uint32_t*)(pam + 24 * XROWB + 16);

                #pragma unroll
                for (int jn = 0; jn < 6; ++jn) {
                    mma_f16(acc[0][jn], a00, a01, a02, a03, b0f[jn], b1f[jn]);
                    mma_f16(acc[1][jn], a10, a11, a12, a13, b0f[jn], b1f[jn]);
                }
            }
        }

        // store this half-window
        const int colb = wn * 48 + 2 * lc;
        #pragma unroll
        for (int mb = 0; mb < 2; ++mb) {
            int rbase = h * HM + wm * 32 + mb * 16 + lane4;
            #pragma unroll
            for (int hh = 0; hh < 2; ++hh) {
                size_t gm = (size_t)(rbase + hh * 8);
                float* op = out + (gm * G_ + g) * O_ + colb;
                #pragma unroll
                for (int jn = 0; jn < 6; ++jn)
                    *(float2*)(op + jn * 8) = make_float2(acc[mb][jn][2 * hh], acc[mb][jn][2 * hh + 1]);
            }
        }
    }
}

extern "C" void kernel_launch(void* const* d_in, const int* in_sizes, int n_in,
                              void* d_out, int out_size)
{
    const float* x    = (const float*)d_in[0];
    const float* wgt  = (const float*)d_in[1];
    const float* bias = (const float*)d_in[2];
    float* out        = (float*)d_out;

    cudaFuncSetAttribute(conv1d_mma_kernel,
                         cudaFuncAttributeMaxDynamicSharedMemorySize, SMEM_TOTAL);

    conv1d_mma_kernel<<<G_, NTHREADS, SMEM_TOTAL>>>(x, wgt, bias, out);
}

// round 15
// speedup vs baseline: 1.4170x; 1.4170x over previous
#include <cuda_runtime.h>
#include <cuda_fp16.h>
#include <cstdint>

#define B_  4
#define T_  512
#define G_  129
#define F_  96
#define O_  96

#define HM  128
#define HROWS 130
#define NWIN 16
#define XROWB 208                       // bytes per fp16 x row: 192 data + 16 pad (conflict-free)
#define XB_BYTES (HROWS * XROWB)        // 27040 per buffer
#define STG_BYTES (HROWS * 96 * 4)      // 49920 fp32 staging per buffer

#define WBLKB 3072                      // per (kk,step) W block: 2 planes x 32 slots x 48B
#define WS_BYTES (18 * WBLKB)           // 55296

#define SM_X0  WS_BYTES
#define SM_ST0 (SM_X0 + 2 * XB_BYTES)
#define SMEM_TOTAL (WS_BYTES + 2 * XB_BYTES + 2 * STG_BYTES)   // 209216

#define NTHREADS 512

__device__ __forceinline__ uint32_t smem_u32(const void* p) {
    uint32_t a;
    asm("{ .reg .u64 t; cvta.to.shared.u64 t, %1; cvt.u32.u64 %0, t; }" : "=r"(a) : "l"(p));
    return a;
}
__device__ __forceinline__ void cp_async16z(uint32_t saddr, const void* gptr, uint32_t src_sz) {
    asm volatile("cp.async.cg.shared.global [%0], [%1], 16, %2;"
                 :: "r"(saddr), "l"(gptr), "r"(src_sz));
}
__device__ __forceinline__ uint32_t pack_f16x2(float lo, float hi) {
    uint32_t r;
    asm("cvt.rn.f16x2.f32 %0, %2, %1;" : "=r"(r) : "f"(lo), "f"(hi));
    return r;
}
__device__ __forceinline__ void mma_f16(float c[4], uint32_t a0, uint32_t a1, uint32_t a2,
                                        uint32_t a3, uint32_t b0, uint32_t b1) {
    asm volatile(
        "mma.sync.aligned.m16n8k16.row.col.f32.f16.f16.f32 "
        "{%0,%1,%2,%3}, {%4,%5,%6,%7}, {%8,%9}, {%0,%1,%2,%3};"
        : "+f"(c[0]), "+f"(c[1]), "+f"(c[2]), "+f"(c[3])
        : "r"(a0), "r"(a1), "r"(a2), "r"(a3), "r"(b0), "r"(b1));
}

__global__ __launch_bounds__(NTHREADS, 1)
void conv1d_mma_kernel(const float* __restrict__ x,
                       const float* __restrict__ w,
                       const float* __restrict__ bias,
                       float* __restrict__ out)
{
    extern __shared__ char smc[];
    char* ws_b = smc;                                   // W fp16, slot layout
    const int tid = threadIdx.x, wid = tid >> 5, lane = tid & 31;
    const int g = blockIdx.x;
    const bool producer = (wid >= 8);
    const int tid2 = tid & 255;
    const int wm = wid & 3, wn = (wid >> 2) & 1;        // consumer: 4 M-warps x 2 N-warps
    const int lane4 = lane >> 2, lc = lane & 31 & 3;

    char*  xbuf[2] = { smc + SM_X0, smc + SM_X0 + XB_BYTES };
    float* stgf[2] = { (float*)(smc + SM_ST0), (float*)(smc + SM_ST0 + STG_BYTES) };
    uint32_t stgs[2] = { smem_u32(stgf[0]), smem_u32(stgf[1]) };

    const float* xg = x + (size_t)g * F_;               // + t*(G_*F_) per row

    // ---- W[g] -> smem fp16 (rn), slot layout, once per CTA (all 512 threads)
    {
        const float4* wg4 = (const float4*)(w + (size_t)g * (O_ * F_ * 3));
        for (int q = tid; q < (O_ * F_ * 3) / 4; q += NTHREADS) {
            float4 v = wg4[q];
            int e = q * 4;
            int o = e / (F_ * 3);
            int rem = e - o * (F_ * 3);                  // o fixed across the 4
            int nblk = o >> 3, orow = o & 7;
            int pos = (nblk < 4) ? nblk : (nblk < 6 ? nblk + 4 : (nblk < 10 ? nblk - 2 : nblk));
            const float* vf = (const float*)&v;
            #pragma unroll
            for (int j = 0; j < 4; ++j) {
                int rr = rem + j;
                int f = rr / 3, kk = rr - 3 * f;
                int s = f >> 4, fh = f & 15;
                int plane = fh >> 3, kp = (fh & 7) >> 1, klo = fh & 1;
                int slot = orow * 4 + kp;
                int off = (kk * 6 + s) * WBLKB + plane * 1536 + slot * 48 + pos * 4 + klo * 2;
                *(__half*)(ws_b + off) = __float2half_rn(vf[j]);
            }
        }
    }

    float bias0[6], bias1[6];

    // ---- prologue: producers stage w0 (converted) + w1 (in flight); consumers load bias
    if (producer) {
        // prefetch window 0 -> stage0
        #pragma unroll 1
        for (int q = tid2; q < HROWS * 24; q += 256) {
            int p = q / 24, c = q - p * 24;
            int t = -1 + p;
            uint32_t ok = (t >= 0 && t < T_) ? 16u : 0u;
            cp_async16z(stgs[0] + p * 384 + c * 16, xg + (size_t)t * (G_ * F_) + c * 4, ok);
        }
        asm volatile("cp.async.commit_group;" ::: "memory");
        asm volatile("cp.async.wait_group 0;" ::: "memory");
        // convert window 0 -> xbuf0
        #pragma unroll 1
        for (int q = tid2; q < HROWS * 24; q += 256) {
            int p = q / 24, c = q - p * 24;
            float4 v = *(const float4*)(stgf[0] + p * 96 + c * 4);
            *(uint2*)(xbuf[0] + p * XROWB + c * 8) =
                make_uint2(pack_f16x2(v.x, v.y), pack_f16x2(v.z, v.w));
        }
        // prefetch window 1 -> stage1
        #pragma unroll 1
        for (int q = tid2; q < HROWS * 24; q += 256) {
            int p = q / 24, c = q - p * 24;
            int t = HM - 1 + p;
            uint32_t ok = (t >= 0 && t < T_) ? 16u : 0u;
            cp_async16z(stgs[1] + p * 384 + c * 16, xg + (size_t)t * (G_ * F_) + c * 4, ok);
        }
        asm volatile("cp.async.commit_group;" ::: "memory");
    } else {
        const float* bg = bias + g * O_ + wn * 48 + 2 * lc;
        #pragma unroll
        for (int jn = 0; jn < 6; ++jn) { bias0[jn] = bg[jn * 8]; bias1[jn] = bg[jn * 8 + 1]; }
    }

    __syncthreads();

    const char* pbl = ws_b + lane * 48;

    // ---- 16 slots: consumers compute window i; producers convert i+1 and prefetch i+2
    for (int i = 0; i < NWIN; ++i) {
        if (producer) {
            if (i < NWIN - 1) {
                asm volatile("cp.async.wait_group 0;" ::: "memory");
                // convert window i+1: stage[(i+1)&1] -> xbuf[(i+1)&1]
                float* sg = stgf[(i + 1) & 1];
                char* xd = xbuf[(i + 1) & 1];
                #pragma unroll 1
                for (int q = tid2; q < HROWS * 24; q += 256) {
                    int p = q / 24, c = q - p * 24;
                    float4 v = *(const float4*)(sg + p * 96 + c * 4);
                    *(uint2*)(xd + p * XROWB + c * 8) =
                        make_uint2(pack_f16x2(v.x, v.y), pack_f16x2(v.z, v.w));
                }
                if (i < NWIN - 2) {
                    // prefetch window i+2 -> stage[i&1]
                    const int hn = i + 2;
                    const int bb = hn >> 2, t0 = (hn & 3) * HM;
                    const float* xgb = xg + (size_t)bb * T_ * G_ * F_;
                    uint32_t sgs = stgs[i & 1];
                    #pragma unroll 1
                    for (int q = tid2; q < HROWS * 24; q += 256) {
                        int p = q / 24, c = q - p * 24;
                        int t = t0 - 1 + p;
                        uint32_t ok = (t >= 0 && t < T_) ? 16u : 0u;
                        cp_async16z(sgs + p * 384 + c * 16, xgb + (size_t)t * (G_ * F_) + c * 4, ok);
                    }
                    asm volatile("cp.async.commit_group;" ::: "memory");
                }
            }
        } else {
            // ---- compute window i
            const char* xb_b = xbuf[i & 1];
            const char* paw = xb_b + (wm * 32 + lane4) * XROWB + lc * 4;

            float acc[2][6][4];
            #pragma unroll
            for (int jn = 0; jn < 6; ++jn) {
                #pragma unroll
                for (int mb = 0; mb < 2; ++mb) {
                    acc[mb][jn][0] = bias0[jn]; acc[mb][jn][1] = bias1[jn];
                    acc[mb][jn][2] = bias0[jn]; acc[mb][jn][3] = bias1[jn];
                }
            }

            #pragma unroll
            for (int kk = 0; kk < 3; ++kk) {
                #pragma unroll
                for (int s = 0; s < 6; ++s) {
                    const char* pbs = pbl + (kk * 6 + s) * WBLKB;
                    uint4 q0 = *(const uint4*)(pbs + wn * 16);
                    uint2 q1 = *(const uint2*)(pbs + 32 + wn * 8);
                    uint4 q2 = *(const uint4*)(pbs + 1536 + wn * 16);
                    uint2 q3 = *(const uint2*)(pbs + 1536 + 32 + wn * 8);
                    uint32_t b0f[6] = { q0.x, q0.y, q0.z, q0.w, q1.x, q1.y };
                    uint32_t b1f[6] = { q2.x, q2.y, q2.z, q2.w, q3.x, q3.y };

                    const char* pam = paw + kk * XROWB + s * 32;
                    uint32_t a00 = *(const uint32_t*)(pam);
                    uint32_t a02 = *(const uint32_t*)(pam + 16);
                    uint32_t a01 = *(const uint32_t*)(pam + 8 * XROWB);
                    uint32_t a03 = *(const uint32_t*)(pam + 8 * XROWB + 16);
                    uint32_t a10 = *(const uint32_t*)(pam + 16 * XROWB);
                    uint32_t a12 = *(const uint32_t*)(pam + 16 * XROWB + 16);
                    uint32_t a11 = *(const uint32_t*)(pam + 24 * XROWB);
                    uint32_t a13 = *(const uint32_t*)(pam + 24 * XROWB + 16);

                    #pragma unroll
                    for (int jn = 0; jn < 6; ++jn) {
                        mma_f16(acc[0][jn], a00, a01, a02, a03, b0f[jn], b1f[jn]);
                        mma_f16(acc[1][jn], a10, a11, a12, a13, b0f[jn], b1f[jn]);
                    }
                }
            }

            // store window i
            const int colb = wn * 48 + 2 * lc;
            #pragma unroll
            for (int mb = 0; mb < 2; ++mb) {
                int rbase = i * HM + wm * 32 + mb * 16 + lane4;
                #pragma unroll
                for (int hh = 0; hh < 2; ++hh) {
                    size_t gm = (size_t)(rbase + hh * 8);
                    float* op = out + (gm * G_ + g) * O_ + colb;
                    #pragma unroll
                    for (int jn = 0; jn < 6; ++jn)
                        *(float2*)(op + jn * 8) =
                            make_float2(acc[mb][jn][2 * hh], acc[mb][jn][2 * hh + 1]);
                }
            }
        }
        __syncthreads();
    }
}

extern "C" void kernel_launch(void* const* d_in, const int* in_sizes, int n_in,
                              void* d_out, int out_size)
{
    const float* x    = (const float*)d_in[0];
    const float* wgt  = (const float*)d_in[1];
    const float* bias = (const float*)d_in[2];
    float* out        = (float*)d_out;

    cudaFuncSetAttribute(conv1d_mma_kernel,
                         cudaFuncAttributeMaxDynamicSharedMemorySize, SMEM_TOTAL);

    conv1d_mma_kernel<<<G_, NTHREADS, SMEM_TOTAL>>>(x, wgt, bias, out);
}